// round 3
// baseline (speedup 1.0000x reference)
#include <cuda_runtime.h>

// Problem: B=2, C=4, D=64, H=256, W=256. Channels 1..3 of pred/trgt used.
// Math: scale(10)/(2*DELTA=10) cancels; vorticity is linear, so compute the
// stencil once on (pred - trgt). Interior crop [1:-1] => all taps in-bounds.
// Keep voxel iff mask==1 and min over 3^3 mask neighborhood == 1.

constexpr int DN = 64, HN = 256, WN = 256;
constexpr long sD = (long)HN * WN;          // 65536
constexpr long sH = WN;                     // 256
constexpr long CS = (long)DN * HN * WN;     // 4194304
constexpr int CHUNK = 16;                   // d-depth per block
constexpr int NCHUNK = 4;                   // ceil(62/16)
constexpr int NPART = 254 * 2 * NCHUNK;     // 2032 partials

__device__ float2 g_part[NPART];

// Grid: (254, 2, NCHUNK), block: 256 (threadIdx.x = w).
__global__ __launch_bounds__(256) void vort_kernel(
    const float* __restrict__ pred,
    const float* __restrict__ trgt,
    const float* __restrict__ mask)
{
    const int tid = threadIdx.x;              // w
    const int h   = blockIdx.x + 1;           // 1..254
    const int b   = blockIdx.y;               // 0..1
    const int c   = blockIdx.z;               // chunk
    const int d0  = 1 + c * CHUNK;
    const int d1  = min(62, d0 + CHUNK - 1);

    // mask row pointer at (b, z=0, h, w)
    const float* mrow = mask + (long)b * DN * sD + (long)h * sH + tid;

    // column-min over y in {-1,0,1} at plane z; also return the center value.
    auto col3 = [&](int z, float& center) -> float {
        const float* p = mrow + (long)z * sD;
        float m0 = __ldg(p - sH);
        float m1 = __ldg(p);
        float m2 = __ldg(p + sH);
        center = m1;
        return fminf(m0, fminf(m1, m2));
    };

    float dummy;
    float cm_prev = col3(d0 - 1, dummy);
    float mc_cur;
    float cm_cur  = col3(d0, mc_cur);

    __shared__ float sh[2][WN];

    float numer = 0.0f;
    float den   = 0.0f;

    const long pbase = (long)b * 4 * CS + (long)h * sH + tid;
    const float* pu = pred + pbase + 1 * CS;
    const float* pv = pred + pbase + 2 * CS;
    const float* pw = pred + pbase + 3 * CS;
    const float* tu = trgt + pbase + 1 * CS;
    const float* tv = trgt + pbase + 2 * CS;
    const float* tw = trgt + pbase + 3 * CS;

    for (int d = d0; d <= d1; d++) {
        float mc_next;
        float cm_next = col3(d + 1, mc_next);

        float cmin = fminf(cm_prev, fminf(cm_cur, cm_next));
        float* buf = sh[d & 1];
        buf[tid] = cmin;
        __syncthreads();   // one sync/iter is safe: read(i) completes before
                           // write(i+2) to same buffer (separated by sync(i+1))

        if (tid >= 1 && tid <= 254 && mc_cur > 0.5f) {
            float nmin = fminf(buf[tid - 1], fminf(cmin, buf[tid + 1]));
            if (nmin > 0.5f) {
                den += 1.0f;
                const long o = (long)d * sD;
                float Du_D = (__ldg(pu + o + sD) - __ldg(tu + o + sD)) - (__ldg(pu + o - sD) - __ldg(tu + o - sD));
                float Du_H = (__ldg(pu + o + sH) - __ldg(tu + o + sH)) - (__ldg(pu + o - sH) - __ldg(tu + o - sH));
                float Dv_D = (__ldg(pv + o + sD) - __ldg(tv + o + sD)) - (__ldg(pv + o - sD) - __ldg(tv + o - sD));
                float Dv_W = (__ldg(pv + o + 1 ) - __ldg(tv + o + 1 )) - (__ldg(pv + o - 1 ) - __ldg(tv + o - 1 ));
                float Dw_H = (__ldg(pw + o + sH) - __ldg(tw + o + sH)) - (__ldg(pw + o - sH) - __ldg(tw + o - sH));
                float Dw_W = (__ldg(pw + o + 1 ) - __ldg(tw + o + 1 )) - (__ldg(pw + o - 1 ) - __ldg(tw + o - 1 ));

                float vx = Dw_H - Dv_D;
                float vy = Du_D - Dw_W;
                float vz = Dv_W - Du_H;
                numer += sqrtf(vx * vx + vy * vy + vz * vz);
            }
        }

        cm_prev = cm_cur;
        cm_cur  = cm_next;
        mc_cur  = mc_next;
    }

    // ---- one block reduction at the end ----
    #pragma unroll
    for (int s = 16; s; s >>= 1) {
        numer += __shfl_down_sync(0xffffffffu, numer, s);
        den   += __shfl_down_sync(0xffffffffu, den,   s);
    }
    __shared__ float wn[8], wd[8];
    const int wid  = tid >> 5;
    const int lane = tid & 31;
    if (lane == 0) { wn[wid] = numer; wd[wid] = den; }
    __syncthreads();
    if (wid == 0) {
        float n2 = (lane < 8) ? wn[lane] : 0.0f;
        float d2 = (lane < 8) ? wd[lane] : 0.0f;
        #pragma unroll
        for (int s = 4; s; s >>= 1) {
            n2 += __shfl_down_sync(0xffffffffu, n2, s);
            d2 += __shfl_down_sync(0xffffffffu, d2, s);
        }
        if (lane == 0) {
            int bid = blockIdx.x + 254 * (blockIdx.y + 2 * blockIdx.z);
            g_part[bid] = make_float2(n2, d2);
        }
    }
}

__global__ __launch_bounds__(1024) void finalize_kernel(float* out) {
    const int t = threadIdx.x;
    double n = 0.0, d = 0.0;
    for (int i = t; i < NPART; i += 1024) {
        float2 p = g_part[i];
        n += (double)p.x;
        d += (double)p.y;
    }
    // warp reduce
    #pragma unroll
    for (int s = 16; s; s >>= 1) {
        n += __shfl_down_sync(0xffffffffu, n, s);
        d += __shfl_down_sync(0xffffffffu, d, s);
    }
    __shared__ double sn[32], sd[32];
    const int wid = t >> 5, lane = t & 31;
    if (lane == 0) { sn[wid] = n; sd[wid] = d; }
    __syncthreads();
    if (wid == 0) {
        n = (lane < 32) ? sn[lane] : 0.0;
        d = (lane < 32) ? sd[lane] : 0.0;
        #pragma unroll
        for (int s = 16; s; s >>= 1) {
            n += __shfl_down_sync(0xffffffffu, n, s);
            d += __shfl_down_sync(0xffffffffu, d, s);
        }
        if (lane == 0) out[0] = (float)(n / d);
    }
}

extern "C" void kernel_launch(void* const* d_in, const int* in_sizes, int n_in,
                              void* d_out, int out_size) {
    const float* pred = (const float*)d_in[0];   // predicts (2,4,64,256,256)
    const float* trgt = (const float*)d_in[1];   // targets  (2,4,64,256,256)
    const float* mask = (const float*)d_in[2];   // masks    (2,1,64,256,256)
    float* out = (float*)d_out;

    dim3 grid(254, 2, NCHUNK);
    vort_kernel<<<grid, 256>>>(pred, trgt, mask);
    finalize_kernel<<<1, 1024>>>(out);
}